// round 16
// baseline (speedup 1.0000x reference)
#include <cuda_runtime.h>

// ---------------------------------------------------------------------------
// ISTFT fused: B=16, NFREQ=513, T=2048, NFFT=1024, HOP=256, WIN=1024, PAD=384
// Kernel A: zero exactly the atomic-stripe samples (k=1..255; fixes OOB).
// Kernel B: 8 frames/block, real-packed 512-pt radix-8 Stockham inverse FFT,
//           affine-padded shared (idx = pos + (pos>>3), base+immediate
//           addressing, conflict-free), register twiddles. Overlap-add is
//           done via 8-lane __shfl (all 4 contributors of a sample share w,
//           differ only in lane f and register m) -> NO y staging, 5 syncs.
//           Interior float2 stores, stripe atomicAdds, sin^4 env at edges.
// ---------------------------------------------------------------------------

#define BATCH     16
#define NFREQ     513
#define TT        2048
#define PAD       384
#define OUT_PER_B 524288                 // (T-1)*HOP + WIN - 2*PAD = 1<<19
#define NFRAMES   (BATCH * TT)           // 32768
#define FPB       8                      // frames per block

// A: 577 padded slots x 8 frames float2 = 9232 floats
#define SM_FLOATS 9232
#define SM_BYTES  (SM_FLOATS * 4)        // 36928 bytes -> 4 blocks/SM

// radix-8 butterfly on 8 complex registers (inverse FFT, +i convention)
__device__ __forceinline__ void bfly8(const float* xr, const float* xi,
                                      float* Xr, float* Xi)
{
    float e0r = xr[0] + xr[4], e0i = xi[0] + xi[4];
    float e1r = xr[0] - xr[4], e1i = xi[0] - xi[4];
    float e2r = xr[2] + xr[6], e2i = xi[2] + xi[6];
    float e3r = xr[2] - xr[6], e3i = xi[2] - xi[6];
    float E0r = e0r + e2r, E0i = e0i + e2i;
    float E2r = e0r - e2r, E2i = e0i - e2i;
    float E1r = e1r - e3i, E1i = e1i + e3r;
    float E3r = e1r + e3i, E3i = e1i - e3r;

    float o0r = xr[1] + xr[5], o0i = xi[1] + xi[5];
    float o1r = xr[1] - xr[5], o1i = xi[1] - xi[5];
    float o2r = xr[3] + xr[7], o2i = xi[3] + xi[7];
    float o3r = xr[3] - xr[7], o3i = xi[3] - xi[7];
    float O0r = o0r + o2r, O0i = o0i + o2i;
    float O2r = o0r - o2r, O2i = o0i - o2i;
    float O1r = o1r - o3i, O1i = o1i + o3r;
    float O3r = o1r + o3i, O3i = o1i - o3r;

    const float RS = 0.70710678118654752440f;
    float c1r = RS * (O1r - O1i), c1i = RS * (O1r + O1i);   // e^{+i pi/4} O1
    float c2r = -O2i,             c2i = O2r;                // i * O2
    float c3r = -RS * (O3r + O3i), c3i = RS * (O3r - O3i);  // e^{+3i pi/4} O3

    Xr[0] = E0r + O0r; Xi[0] = E0i + O0i;
    Xr[4] = E0r - O0r; Xi[4] = E0i - O0i;
    Xr[1] = E1r + c1r; Xi[1] = E1i + c1i;
    Xr[5] = E1r - c1r; Xi[5] = E1i - c1i;
    Xr[2] = E2r + c2r; Xi[2] = E2i + c2i;
    Xr[6] = E2r - c2r; Xi[6] = E2i - c2i;
    Xr[3] = E3r + c3r; Xi[3] = E3i + c3i;
    Xr[7] = E3r - c3r; Xi[7] = E3i - c3i;
}

// zero exactly the stripe float4s: per batch 255*192 = 48960 (k = 1..255)
__global__ void __launch_bounds__(256)
istft_zero_kernel(float4* __restrict__ out4)
{
    unsigned idx = blockIdx.x * 256u + threadIdx.x;   // < 783360 exactly
    unsigned b = idx / 48960u;
    unsigned r = idx - b * 48960u;
    unsigned k = r / 192u + 1u;                       // 8-frame period 1..255
    unsigned j = r - (k - 1u) * 192u;
    out4[b * 131072u + (k << 9) - 96u + j] = make_float4(0.f, 0.f, 0.f, 0.f);
}

__global__ void __launch_bounds__(512, 4)
istft_fused_kernel(const float* __restrict__ spr,
                   const float* __restrict__ spi,
                   const float* __restrict__ win,
                   float* __restrict__ out)
{
    extern __shared__ float sm[];
    float2* A = (float2*)sm;    // padded FFT buffer: A[idx(pos)*8 + f]

    const int tid = threadIdx.x;
    const int f   = tid & 7;    // frame lane
    const int w   = tid >> 3;   // worker 0..63

    // affine address bases (all shared accesses become base + immediate)
    const int iw  = w + (w >> 3);                 // idx(w + 64j) = iw + 72j
    const int imw = 575 - w - ((w - 1) >> 3);     // idx(512-w-64m) = imw - 72m
    float2* Aw  = A + iw * 8 + f;                 // stage/spectrum base
    float2* Amw = A + imw * 8 + f;                // mirror base
    float2* As1 = A + (9 * w) * 8 + f;            // stage-1 write base
    const int h = w >> 3;
    float2* As2 = A + (72 * h + (w & 7)) * 8 + f; // stage-2 write base

    // register twiddle bases
    float zwr, zwi;   // e^{+2pi i w/1024}
    __sincosf((float)w * 6.1359231515e-3f, &zwi, &zwr);
    float w1r = fmaf(zwr, zwr, -zwi * zwi);   // e^{+2pi i w/512}
    float w1i = 2.0f * zwr * zwi;
    float bhr, bhi;   // e^{+2pi i h/64}
    __sincosf((float)h * 9.8174770424e-2f, &bhi, &bhr);

    const int fr0 = blockIdx.x * FPB;
    const int b   = fr0 >> 11;
    const int t0  = fr0 & 2047;
    const float* pr  = spr + (size_t)b * NFREQ * TT + (t0 + f);
    const float* pim = spi + (size_t)b * NFREQ * TT + (t0 + f);

    // ---- load X[0..511] into A; X[512] in register on w==0 threads ----
    #pragma unroll
    for (int m = 0; m < 8; m++) {
        int k = w + (m << 6);
        float re = __ldg(pr  + k * TT);
        float im = __ldg(pim + k * TT);
        if (k == 0) im = 0.0f;
        Aw[576 * m] = make_float2(re, im);     // idx step 72 -> float2 step 576
    }
    float x512r = 0.0f;
    if (w == 0) x512r = __ldg(pr + 512 * TT);
    __syncthreads();

    float vr[8], vi[8];

    // ---- Hermitian packing Z[k]=E+iO (k = w+64m); twiddle chain from zw ----
    {
        const float S16r = 0.92387953251128675613f;  // e^{+2pi i/16}
        const float S16i = 0.38268343236508977173f;
        float ct = zwr, st = zwi;
        #pragma unroll
        for (int m = 0; m < 8; m++) {
            float2 zk = Aw[576 * m];
            float xcr, xci;
            if (w == 0 && m == 0) { xcr = x512r; xci = 0.0f; }
            else { float2 zc = Amw[-576 * m]; xcr = zc.x; xci = zc.y; }
            float Er = 0.5f * (zk.x + xcr);
            float Ei = 0.5f * (zk.y - xci);
            float Dr = 0.5f * (zk.x - xcr);
            float Di = 0.5f * (zk.y + xci);
            float Or = fmaf(ct, Dr, -st * Di);
            float Oi = fmaf(ct, Di,  st * Dr);
            vr[m] = Er - Oi;
            vi[m] = Ei + Or;
            float nc = fmaf(ct, S16r, -st * S16i);   // rotate by e^{2pi i/16}
            float ns = fmaf(ct, S16i,  st * S16r);
            ct = nc; st = ns;
        }
    }
    __syncthreads();   // packing reads done -> safe to overwrite A

    // ---- stage 1 (S=1): regs -> A at idx 9w+m, twiddle w1^m ----
    {
        float Xr[8], Xi[8];
        bfly8(vr, vi, Xr, Xi);
        As1[0] = make_float2(Xr[0], Xi[0]);
        float cr = w1r, ci = w1i;
        #pragma unroll
        for (int m = 1; m < 8; m++) {
            As1[8 * m] = make_float2(fmaf(Xr[m], cr, -Xi[m] * ci),
                                     fmaf(Xr[m], ci,  Xi[m] * cr));
            float nc = fmaf(cr, w1r, -ci * w1i);
            float ns = fmaf(cr, w1i,  ci * w1r);
            cr = nc; ci = ns;
        }
    }
    __syncthreads();

    // ---- stage 2 (S=8): A -> regs -> A at idx 72h+q+9m, twiddle bh^m ----
    {
        #pragma unroll
        for (int j = 0; j < 8; j++) {
            float2 z = Aw[576 * j];
            vr[j] = z.x; vi[j] = z.y;
        }
        __syncthreads();
        float Xr[8], Xi[8];
        bfly8(vr, vi, Xr, Xi);
        As2[0] = make_float2(Xr[0], Xi[0]);
        float cr = bhr, ci = bhi;
        #pragma unroll
        for (int m = 1; m < 8; m++) {
            As2[72 * m] = make_float2(fmaf(Xr[m], cr, -Xi[m] * ci),
                                      fmaf(Xr[m], ci,  Xi[m] * cr));
            float nc = fmaf(cr, bhr, -ci * bhi);
            float ns = fmaf(cr, bhi,  ci * bhr);
            cr = nc; ci = ns;
        }
    }
    __syncthreads();

    // ---- stage 3 (S=64): A -> regs -> butterfly -> windowed V in regs ----
    #pragma unroll
    for (int j = 0; j < 8; j++) {
        float2 z = Aw[576 * j];
        vr[j] = z.x; vi[j] = z.y;
    }
    // no further shared use -> no sync needed

    float Vx[8], Vy[8];   // V[m] = windowed sample at pos 2n(,+1), n = w+64m
    {
        float Xr[8], Xi[8];
        bfly8(vr, vi, Xr, Xi);
        const float2* w2 = (const float2*)win;
        const float inv = 1.0f / 512.0f;
        #pragma unroll
        for (int m = 0; m < 8; m++) {
            float2 wv = __ldg(w2 + w + (m << 6));
            Vx[m] = Xr[m] * inv * wv.x;
            Vy[m] = Xi[m] * inv * wv.y;
        }
    }

    // ---- shuffle OLA: output(fl, eps, par, w) = sum_j V[eps+2j] of lane fl-j
    // acc: interior (f>=3) full sums / bottom (f<3) partials (j<=f)
    // at : top partials for fl = 8+f (f<3), lanes (f-j)&7 wrap to 5..7
    float acc[2][2] = {{0.f, 0.f}, {0.f, 0.f}};
    float at [2][2] = {{0.f, 0.f}, {0.f, 0.f}};
    #pragma unroll
    for (int j = 0; j < 4; j++) {
        int src = (f - j) & 7;
        #pragma unroll
        for (int e = 0; e < 2; e++) {
            float sx = __shfl_sync(0xffffffffu, Vx[2 * j + e], src, 8);
            float sy = __shfl_sync(0xffffffffu, Vy[2 * j + e], src, 8);
            if (f >= j) { acc[e][0] += sx; acc[e][1] += sy; }
            else        { at [e][0] += sx; at [e][1] += sy; }
        }
    }

    float* outb = out + (size_t)b * OUT_PER_B;
    const float TW3 = 2.0f / 3.0f;
    const float PI1024 = 3.0679615757712823e-3f;   // pi/1024

    if (f >= 3) {
        // interior: env == 1.5 exactly (Hann, hop = N/4, 4 frames)
        float* p = outb + ((t0 + f) << 8) + 2 * w - PAD;
        *(float2*)(p)       = make_float2(acc[0][0] * TW3, acc[0][1] * TW3);
        *(float2*)(p + 128) = make_float2(acc[1][0] * TW3, acc[1][1] * TW3);
    } else {
        if (t0 != 0) {
            // bottom stripe partial -> atomics (pre-zeroed)
            float* p = outb + ((t0 + f) << 8) + 2 * w - PAD;
            atomicAdd(p,       acc[0][0] * TW3);
            atomicAdd(p + 1,   acc[0][1] * TW3);
            atomicAdd(p + 128, acc[1][0] * TW3);
            atomicAdd(p + 129, acc[1][1] * TW3);
        } else {
            // batch start: direct store with explicit env (frames 0..f only)
            #pragma unroll
            for (int e = 0; e < 2; e++)
            #pragma unroll
            for (int par = 0; par < 2; par++) {
                int pos = 2 * w + 128 * e + par;
                int l = (f << 8) + pos;
                if (l >= PAD) {
                    float env = 0.f;
                    for (int j = 0; j <= f; j++) {
                        float s = __sinf((float)(pos + 256 * j) * PI1024);
                        float s2 = s * s;
                        env = fmaf(s2, s2, env);   // win^2 = sin^4
                    }
                    outb[l - PAD] = acc[e][par] / env;
                }
            }
        }
        if (t0 != 2040) {
            // top stripe partial -> atomics (pre-zeroed)
            float* p = outb + ((t0 + 8 + f) << 8) + 2 * w - PAD;
            atomicAdd(p,       at[0][0] * TW3);
            atomicAdd(p + 1,   at[0][1] * TW3);
            atomicAdd(p + 128, at[1][0] * TW3);
            atomicAdd(p + 129, at[1][1] * TW3);
        } else {
            // batch end: direct store with explicit env (frames 2045+f..2047)
            #pragma unroll
            for (int e = 0; e < 2; e++)
            #pragma unroll
            for (int par = 0; par < 2; par++) {
                int pos = 2 * w + 128 * e + par;
                int l = 524288 + (f << 8) + pos;
                if ((f << 8) + pos < PAD) {
                    float env = 0.f;
                    for (int j = f + 1; j <= 3; j++) {
                        float s = __sinf((float)(pos + 256 * j) * PI1024);
                        float s2 = s * s;
                        env = fmaf(s2, s2, env);
                    }
                    outb[l - PAD] = at[e][par] / env;
                }
            }
        }
    }
}

extern "C" void kernel_launch(void* const* d_in, const int* in_sizes, int n_in,
                              void* d_out, int out_size)
{
    const float* spr = (const float*)d_in[0];
    const float* spi = (const float*)d_in[1];
    const float* win = (const float*)d_in[2];
    float* out = (float*)d_out;

    cudaFuncSetAttribute(istft_fused_kernel,
                         cudaFuncAttributeMaxDynamicSharedMemorySize, SM_BYTES);

    istft_zero_kernel<<<3060, 256>>>((float4*)out);
    istft_fused_kernel<<<NFRAMES / FPB, 512, SM_BYTES>>>(spr, spi, win, out);
}

// round 17
// speedup vs baseline: 1.1400x; 1.1400x over previous
#include <cuda_runtime.h>

// ---------------------------------------------------------------------------
// ISTFT fused: B=16, NFREQ=513, T=2048, NFFT=1024, HOP=256, WIN=1024, PAD=384
// Kernel A: zero exactly the atomic-stripe samples (k=1..255; no OOB).
// Kernel B: 8 frames/block, real-packed 512-pt radix-8 Stockham inverse FFT.
//           Affine-padded shared (idx = pos + (pos>>3): base+immediate
//           addressing, conflict-free). Own spectrum values stay in
//           registers across the staging sync (packing reads ONLY mirrors
//           from shared). Register twiddles, windowed frames staged in
//           shared, overlap-add direct to out (float4 interior stores,
//           2-way atomicAdd stripes, explicit env at batch edges).
//           __launch_bounds__(512,4) pins 4 blocks/SM.
// ---------------------------------------------------------------------------

#define BATCH     16
#define NFREQ     513
#define TT        2048
#define PAD       384
#define OUT_PER_B 524288                 // (T-1)*HOP + WIN - 2*PAD = 1<<19
#define NFRAMES   (BATCH * TT)           // 32768
#define FPB       8                      // frames per block
#define YPITCH    1028                   // 1028 % 32 == 4 -> bank-perm rows

// A: 577 padded slots x 8 frames float2 = 9232 floats; y: 8224 floats (fits)
#define SM_FLOATS 9232
#define SM_BYTES  (SM_FLOATS * 4)        // 36928 bytes -> 4 blocks/SM

// radix-8 butterfly on 8 complex registers (inverse FFT, +i convention)
__device__ __forceinline__ void bfly8(const float* xr, const float* xi,
                                      float* Xr, float* Xi)
{
    float e0r = xr[0] + xr[4], e0i = xi[0] + xi[4];
    float e1r = xr[0] - xr[4], e1i = xi[0] - xi[4];
    float e2r = xr[2] + xr[6], e2i = xi[2] + xi[6];
    float e3r = xr[2] - xr[6], e3i = xi[2] - xi[6];
    float E0r = e0r + e2r, E0i = e0i + e2i;
    float E2r = e0r - e2r, E2i = e0i - e2i;
    float E1r = e1r - e3i, E1i = e1i + e3r;
    float E3r = e1r + e3i, E3i = e1i - e3r;

    float o0r = xr[1] + xr[5], o0i = xi[1] + xi[5];
    float o1r = xr[1] - xr[5], o1i = xi[1] - xi[5];
    float o2r = xr[3] + xr[7], o2i = xi[3] + xi[7];
    float o3r = xr[3] - xr[7], o3i = xi[3] - xi[7];
    float O0r = o0r + o2r, O0i = o0i + o2i;
    float O2r = o0r - o2r, O2i = o0i - o2i;
    float O1r = o1r - o3i, O1i = o1i + o3r;
    float O3r = o1r + o3i, O3i = o1i - o3r;

    const float RS = 0.70710678118654752440f;
    float c1r = RS * (O1r - O1i), c1i = RS * (O1r + O1i);   // e^{+i pi/4} O1
    float c2r = -O2i,             c2i = O2r;                // i * O2
    float c3r = -RS * (O3r + O3i), c3i = RS * (O3r - O3i);  // e^{+3i pi/4} O3

    Xr[0] = E0r + O0r; Xi[0] = E0i + O0i;
    Xr[4] = E0r - O0r; Xi[4] = E0i - O0i;
    Xr[1] = E1r + c1r; Xi[1] = E1i + c1i;
    Xr[5] = E1r - c1r; Xi[5] = E1i - c1i;
    Xr[2] = E2r + c2r; Xi[2] = E2i + c2i;
    Xr[6] = E2r - c2r; Xi[6] = E2i - c2i;
    Xr[3] = E3r + c3r; Xi[3] = E3i + c3i;
    Xr[7] = E3r - c3r; Xi[7] = E3i - c3i;
}

// zero exactly the stripe float4s: per batch 255*192 = 48960 (k = 1..255)
__global__ void __launch_bounds__(256)
istft_zero_kernel(float4* __restrict__ out4)
{
    unsigned idx = blockIdx.x * 256u + threadIdx.x;   // < 783360 exactly
    unsigned b = idx / 48960u;
    unsigned r = idx - b * 48960u;
    unsigned k = r / 192u + 1u;                       // 8-frame period 1..255
    unsigned j = r - (k - 1u) * 192u;
    out4[b * 131072u + (k << 9) - 96u + j] = make_float4(0.f, 0.f, 0.f, 0.f);
}

__global__ void __launch_bounds__(512, 4)
istft_fused_kernel(const float* __restrict__ spr,
                   const float* __restrict__ spi,
                   const float* __restrict__ win,
                   float* __restrict__ out)
{
    extern __shared__ float sm[];
    float2* A = (float2*)sm;    // padded FFT buffer: A[idx(pos)*8 + f]
    float*  y = sm;             // frame staging overlays A: 8*YPITCH floats

    const int tid = threadIdx.x;
    const int f   = tid & 7;    // frame lane
    const int w   = tid >> 3;   // worker 0..63

    // affine address bases (all shared accesses become base + immediate)
    const int iw  = w + (w >> 3);                 // idx(w + 64j) = iw + 72j
    const int imw = 575 - w - ((w - 1) >> 3);     // idx(512-w-64m) = imw - 72m
    float2* Aw  = A + iw * 8 + f;                 // stage/spectrum base
    float2* Amw = A + imw * 8 + f;                // mirror base
    float2* As1 = A + (9 * w) * 8 + f;            // stage-1 write base
    const int h = w >> 3;
    float2* As2 = A + (72 * h + (w & 7)) * 8 + f; // stage-2 write base

    // register twiddle bases
    float zwr, zwi;   // e^{+2pi i w/1024}
    __sincosf((float)w * 6.1359231515e-3f, &zwi, &zwr);
    float w1r = fmaf(zwr, zwr, -zwi * zwi);   // e^{+2pi i w/512}
    float w1i = 2.0f * zwr * zwi;
    float bhr, bhi;   // e^{+2pi i h/64}
    __sincosf((float)h * 9.8174770424e-2f, &bhi, &bhr);

    const int fr0 = blockIdx.x * FPB;
    const int b   = fr0 >> 11;
    const int t0  = fr0 & 2047;
    const float* pr  = spr + (size_t)b * NFREQ * TT + (t0 + f);
    const float* pim = spi + (size_t)b * NFREQ * TT + (t0 + f);

    float vr[8], vi[8];   // X[w+64m] lives here, overwritten by Z in packing

    // ---- load X[0..511]: keep own values in regs AND stage for mirrors ----
    #pragma unroll
    for (int m = 0; m < 8; m++) {
        int k = w + (m << 6);
        vr[m] = __ldg(pr  + k * TT);
        vi[m] = (k == 0) ? 0.0f : __ldg(pim + k * TT);
        Aw[576 * m] = make_float2(vr[m], vi[m]);   // idx step 72 -> f2 step 576
    }
    float x512r = 0.0f;
    if (w == 0) x512r = __ldg(pr + 512 * TT);
    __syncthreads();

    // ---- Hermitian packing Z[k]=E+iO (k = w+64m); mirrors from shared ----
    {
        const float S16r = 0.92387953251128675613f;  // e^{+2pi i/16}
        const float S16i = 0.38268343236508977173f;
        float ct = zwr, st = zwi;
        #pragma unroll
        for (int m = 0; m < 8; m++) {
            float xcr, xci;
            if (w == 0 && m == 0) { xcr = x512r; xci = 0.0f; }
            else { float2 zc = Amw[-576 * m]; xcr = zc.x; xci = zc.y; }
            float Er = 0.5f * (vr[m] + xcr);
            float Ei = 0.5f * (vi[m] - xci);
            float Dr = 0.5f * (vr[m] - xcr);
            float Di = 0.5f * (vi[m] + xci);
            float Or = fmaf(ct, Dr, -st * Di);
            float Oi = fmaf(ct, Di,  st * Dr);
            vr[m] = Er - Oi;                         // Z overwrites X in place
            vi[m] = Ei + Or;
            float nc = fmaf(ct, S16r, -st * S16i);   // rotate by e^{2pi i/16}
            float ns = fmaf(ct, S16i,  st * S16r);
            ct = nc; st = ns;
        }
    }
    __syncthreads();   // all mirror reads done -> safe to overwrite A

    // ---- stage 1 (S=1): regs -> A at idx 9w+m, twiddle w1^m ----
    {
        float Xr[8], Xi[8];
        bfly8(vr, vi, Xr, Xi);
        As1[0] = make_float2(Xr[0], Xi[0]);
        float cr = w1r, ci = w1i;
        #pragma unroll
        for (int m = 1; m < 8; m++) {
            As1[8 * m] = make_float2(fmaf(Xr[m], cr, -Xi[m] * ci),
                                     fmaf(Xr[m], ci,  Xi[m] * cr));
            float nc = fmaf(cr, w1r, -ci * w1i);
            float ns = fmaf(cr, w1i,  ci * w1r);
            cr = nc; ci = ns;
        }
    }
    __syncthreads();

    // ---- stage 2 (S=8): A -> regs -> A at idx 72h+q+9m, twiddle bh^m ----
    {
        #pragma unroll
        for (int j = 0; j < 8; j++) {
            float2 z = Aw[576 * j];
            vr[j] = z.x; vi[j] = z.y;
        }
        __syncthreads();
        float Xr[8], Xi[8];
        bfly8(vr, vi, Xr, Xi);
        As2[0] = make_float2(Xr[0], Xi[0]);
        float cr = bhr, ci = bhi;
        #pragma unroll
        for (int m = 1; m < 8; m++) {
            As2[72 * m] = make_float2(fmaf(Xr[m], cr, -Xi[m] * ci),
                                      fmaf(Xr[m], ci,  Xi[m] * cr));
            float nc = fmaf(cr, bhr, -ci * bhi);
            float ns = fmaf(cr, bhi,  ci * bhr);
            cr = nc; ci = ns;
        }
    }
    __syncthreads();

    // ---- stage 3 (S=64): A -> regs; windowed frames -> y[f][pos] ----
    #pragma unroll
    for (int j = 0; j < 8; j++) {
        float2 z = Aw[576 * j];
        vr[j] = z.x; vi[j] = z.y;
    }
    __syncthreads();   // reads done -> y may overwrite A
    {
        float Xr[8], Xi[8];
        bfly8(vr, vi, Xr, Xi);
        const float2* w2 = (const float2*)win;
        const float inv = 1.0f / 512.0f;
        float* yf = y + f * YPITCH + 2 * w;
        #pragma unroll
        for (int m = 0; m < 8; m++) {
            float2 wv = __ldg(w2 + w + (m << 6));
            float2 o;
            o.x = Xr[m] * inv * wv.x;
            o.y = Xi[m] * inv * wv.y;
            *(float2*)(yf + 128 * m) = o;      // pos 2n, 2n+1 (n = w + 64m)
        }
    }
    __syncthreads();

    // =================== overlap-add from shared ===================
    float* outb = out + (size_t)b * OUT_PER_B;
    const float TW3 = 2.0f / 3.0f;

    // interior-owned: tmax in [t0+3, t0+7]; 1280 samples as 320 float4
    if (tid < 320) {
        int fl  = 3 + (tid >> 6);          // tmax - t0, 3..7
        int pos = (tid & 63) << 2;         // 0..252, step 4
        const float* yb = y + pos;
        float4 a0 = *(const float4*)(yb + (fl - 3) * YPITCH + 768);
        float4 a1 = *(const float4*)(yb + (fl - 2) * YPITCH + 512);
        float4 a2 = *(const float4*)(yb + (fl - 1) * YPITCH + 256);
        float4 a3 = *(const float4*)(yb +  fl      * YPITCH);
        float4 r;
        r.x = (a0.x + a1.x + a2.x + a3.x) * TW3;
        r.y = (a0.y + a1.y + a2.y + a3.y) * TW3;
        r.z = (a0.z + a1.z + a2.z + a3.z) * TW3;
        r.w = (a0.w + a1.w + a2.w + a3.w) * TW3;
        *(float4*)(outb + ((t0 + fl) << 8) + pos - PAD) = r;
    }

    if (t0 != 0) {
        // bottom stripe: l in [256 t0, 256 t0 + 768)
        for (int s = tid; s < 768; s += 512) {
            int r = s >> 8;                // tmax - t0: 0,1,2
            float acc = y[s];
            if (r >= 1) acc += y[1 * YPITCH + s - 256];
            if (r >= 2) acc += y[2 * YPITCH + s - 512];
            atomicAdd(outb + (t0 << 8) + s - PAD, acc * TW3);
        }
    } else {
        // batch start: l in [384, 768), env varies
        if (tid < 384) {
            int l = PAD + tid;
            int tmax = l >> 8;             // 1 or 2
            float acc = 0.0f, env = 0.0f;
            for (int t = 0; t <= tmax; t++) {
                int pos = l - (t << 8);
                float wv = __ldg(win + pos);
                env = fmaf(wv, wv, env);
                acc += y[t * YPITCH + pos];
            }
            outb[l - PAD] = acc / env;
        }
    }

    if (t0 != 2040) {
        // top stripe: l in [256(t0+8), +768)
        for (int s = tid; s < 768; s += 512) {
            int r = s >> 8;                // 0,1,2 ; count = 3 - r
            float acc = y[7 * YPITCH + s + 256];
            if (r <= 1) acc += y[6 * YPITCH + s + 512];
            if (r == 0) acc += y[5 * YPITCH + s + 768];
            atomicAdd(outb + ((t0 + 8) << 8) + s - PAD, acc * TW3);
        }
    } else {
        // batch end: l in [524288, 524672)
        if (tid < 384) {
            int l = 524288 + tid;
            int tmin = (l - 768) >> 8;     // 2045..2046
            float acc = 0.0f, env = 0.0f;
            for (int t = tmin; t <= 2047; t++) {
                int pos = l - (t << 8);
                float wv = __ldg(win + pos);
                env = fmaf(wv, wv, env);
                acc += y[(t - 2040) * YPITCH + pos];
            }
            outb[l - PAD] = acc / env;
        }
    }
}

extern "C" void kernel_launch(void* const* d_in, const int* in_sizes, int n_in,
                              void* d_out, int out_size)
{
    const float* spr = (const float*)d_in[0];
    const float* spi = (const float*)d_in[1];
    const float* win = (const float*)d_in[2];
    float* out = (float*)d_out;

    cudaFuncSetAttribute(istft_fused_kernel,
                         cudaFuncAttributeMaxDynamicSharedMemorySize, SM_BYTES);

    istft_zero_kernel<<<3060, 256>>>((float4*)out);
    istft_fused_kernel<<<NFRAMES / FPB, 512, SM_BYTES>>>(spr, spi, win, out);
}